// round 9
// baseline (speedup 1.0000x reference)
#include <cuda_runtime.h>
#include <cuda_fp16.h>
#include <cstdint>
#include <cstddef>

// Problem sizes (fixed by the dataset)
static constexpr int TOKENS = 8192;
static constexpr int INDIM  = 4096;
static constexpr int OUTDIM = 4096;
static constexpr int GROUPS = 32;      // INDIM / 128

// fp16 staging buffers (static device allocs are allowed; cudaMalloc is not)
__device__ __half g_Xh[(size_t)TOKENS * INDIM];   // 64 MB
__device__ __half g_Wh[(size_t)OUTDIM * INDIM];   // 32 MB

// ---------------------------------------------------------------------------
// Fused prologue: blocks [0, XBLK) convert x -> fp16; the rest dequantize W.
// Single kernel so the harness launch sequence is [prep, gemm] per call
// (aligns ncu -s 5 onto the GEMM) and one launch overhead is saved.
// ---------------------------------------------------------------------------
static constexpr int XBLK = (TOKENS * (INDIM / 4)) / 256;    // 32768
static constexpr int WBLK = (OUTDIM * (INDIM / 4)) / 256;    // 16384

__global__ void __launch_bounds__(256)
prep_kernel(const float* __restrict__ x, const int* __restrict__ Q,
            const float* __restrict__ scales) {
    if (blockIdx.x < XBLK) {
        size_t i = (size_t)blockIdx.x * 256 + threadIdx.x;     // float4 index
        float4 v = reinterpret_cast<const float4*>(x)[i];
        __half2 h0 = __floats2half2_rn(v.x, v.y);
        __half2 h1 = __floats2half2_rn(v.z, v.w);
        uint2 u;
        u.x = *reinterpret_cast<uint32_t*>(&h0);
        u.y = *reinterpret_cast<uint32_t*>(&h1);
        reinterpret_cast<uint2*>(g_Xh)[i] = u;
    } else {
        size_t i = (size_t)(blockIdx.x - XBLK) * 256 + threadIdx.x;  // int4 idx
        int4 q = reinterpret_cast<const int4*>(Q)[i];
        size_t lin = i * 4;
        int o = (int)(lin >> 12);            // / 4096
        int k = (int)(lin & 4095);
        float s = __ldg(scales + o * GROUPS + (k >> 7));
        __half2 h0 = __floats2half2_rn((float)q.x * s, (float)q.y * s);
        __half2 h1 = __floats2half2_rn((float)q.z * s, (float)q.w * s);
        uint2 u;
        u.x = *reinterpret_cast<uint32_t*>(&h0);
        u.y = *reinterpret_cast<uint32_t*>(&h1);
        reinterpret_cast<uint2*>(g_Wh)[i] = u;
    }
}

// ---------------------------------------------------------------------------
// Helpers
// ---------------------------------------------------------------------------
__device__ __forceinline__ uint32_t smem_u32(const void* p) {
    uint32_t a;
    asm("{ .reg .u64 t; cvta.to.shared.u64 t, %1; cvt.u32.u64 %0, t; }"
        : "=r"(a) : "l"(p));
    return a;
}

__device__ __forceinline__ uint32_t sw128(uint32_t o) {
    return o ^ ((o >> 3) & 0x70);
}

__device__ __forceinline__ void ldsm_x4(uint32_t* r, uint32_t addr) {
    asm volatile("ldmatrix.sync.aligned.m8n8.x4.shared.b16 {%0,%1,%2,%3}, [%4];"
                 : "=r"(r[0]), "=r"(r[1]), "=r"(r[2]), "=r"(r[3])
                 : "r"(addr));
}

__device__ __forceinline__ void mma16816(float* c, const uint32_t* a,
                                         const uint32_t* b) {
    asm volatile(
        "mma.sync.aligned.m16n8k16.row.col.f32.f16.f16.f32 "
        "{%0,%1,%2,%3}, {%4,%5,%6,%7}, {%8,%9}, {%0,%1,%2,%3};"
        : "+f"(c[0]), "+f"(c[1]), "+f"(c[2]), "+f"(c[3])
        : "r"(a[0]), "r"(a[1]), "r"(a[2]), "r"(a[3]), "r"(b[0]), "r"(b[1]));
}

// ---------------------------------------------------------------------------
// GEMM: C[8192,4096] = Xh @ Wh^T + bias
// BM=128, BN=256, BK=64, 4 stages, 256 threads (8 warps, 2x4), warp tile 64x64
// ---------------------------------------------------------------------------
static constexpr int BM = 128;
static constexpr int BN = 256;
static constexpr int BK = 64;                 // halves; 128 bytes per row
static constexpr int STAGES = 4;
static constexpr int KITERS = INDIM / BK;     // 64
static constexpr int A_BYTES = BM * 128;      // 16384
static constexpr int STAGE_BYTES = A_BYTES + BN * 128;  // 49152
static constexpr int SMEM_BYTES = STAGES * STAGE_BYTES + 1024;  // 197632

__global__ void __launch_bounds__(256, 1)
gemm_kernel(float* __restrict__ out, const float* __restrict__ bias) {
    extern __shared__ char smem[];
    const uint32_t sb = (smem_u32(smem) + 1023u) & ~1023u;
    const int tid  = threadIdx.x;
    const int lane = tid & 31;
    const int wid  = tid >> 5;
    const int wm   = wid >> 2;    // 0..1
    const int wn   = wid & 3;     // 0..3
    const int n0   = blockIdx.x * BN;
    const int m0   = blockIdx.y * BM;

    // Stage loader: A 1024 + B 2048 16B-chunks over 256 threads (12 each)
    auto load_stage = [&](int s, int kiter) {
        const int k0 = kiter * BK;
        const uint32_t st = sb + s * STAGE_BYTES;
        #pragma unroll
        for (int c = tid; c < 3072; c += 256) {
            const int ch = c & 7;                 // 16B chunk within 128B row
            const __half* g;
            uint32_t soff;
            if (c < 1024) {                       // A rows m0..m0+127
                const int r = c >> 3;
                g = g_Xh + (size_t)(m0 + r) * INDIM + k0 + ch * 8;
                soff = st + sw128((uint32_t)(r * 128 + ch * 16));
            } else {                              // B rows n0..n0+255
                const int r = (c - 1024) >> 3;
                g = g_Wh + (size_t)(n0 + r) * INDIM + k0 + ch * 8;
                soff = st + A_BYTES + sw128((uint32_t)(r * 128 + ch * 16));
            }
            asm volatile("cp.async.cg.shared.global [%0], [%1], 16;"
                         :: "r"(soff), "l"(g) : "memory");
        }
        asm volatile("cp.async.commit_group;" ::: "memory");
    };

    // Per-thread ldmatrix address components
    const int a_row = lane & 15;                       // 0..15
    const int a_col = (lane >> 4) << 4;                // 0 or 16 bytes
    const uint32_t a_xor = (uint32_t)((a_row & 7) << 4);
    const int b_row = ((lane >> 4) << 3) | (lane & 7); // 0..15
    const int b_col = ((lane >> 3) & 1) << 4;          // 0 or 16 bytes
    const uint32_t b_xor = (uint32_t)((b_row & 7) << 4);

    float acc[4][8][4];
    #pragma unroll
    for (int mt = 0; mt < 4; mt++)
        #pragma unroll
        for (int n = 0; n < 8; n++)
            #pragma unroll
            for (int j = 0; j < 4; j++) acc[mt][n][j] = 0.0f;

    // Prologue: 3 stages in flight
    load_stage(0, 0);
    load_stage(1, 1);
    load_stage(2, 2);

    // Main loop, unrolled x4 so stage indices are compile-time constants.
    for (int it = 0; it < KITERS; it += STAGES) {
        #pragma unroll
        for (int u = 0; u < STAGES; u++) {
            const int i = it + u;
            asm volatile("cp.async.wait_group 2;" ::: "memory");
            __syncthreads();

            // Prefetch stage (i+3)%4 (freed by the barrier above)
            if (i + 3 < KITERS) {
                load_stage((u + 3) & 3, i + 3);
            } else {
                asm volatile("cp.async.commit_group;" ::: "memory");
            }

            // Compute on stage u with ks-level register double buffering
            const uint32_t stg = sb + u * STAGE_BYTES;
            const uint32_t aT = stg + (uint32_t)((wm * 64 + a_row) * 128);
            const uint32_t bT = stg + A_BYTES + (uint32_t)((wn * 64 + b_row) * 128);

            uint32_t af[2][4][4], bf[2][4][4];
            // Preload ks = 0 fragments
            #pragma unroll
            for (int mt = 0; mt < 4; mt++)
                ldsm_x4(af[0][mt], aT + (uint32_t)(mt * 16 * 128)
                                      + (((uint32_t)a_col) ^ a_xor));
            #pragma unroll
            for (int nt = 0; nt < 4; nt++)
                ldsm_x4(bf[0][nt], bT + (uint32_t)(nt * 16 * 128)
                                      + (((uint32_t)b_col) ^ b_xor));

            #pragma unroll
            for (int ks = 0; ks < 4; ks++) {
                const int cur = ks & 1, nxt = cur ^ 1;
                if (ks < 3) {   // prefetch ks+1 fragments ahead of the MMAs
                    #pragma unroll
                    for (int mt = 0; mt < 4; mt++)
                        ldsm_x4(af[nxt][mt],
                                aT + (uint32_t)(mt * 16 * 128)
                                   + (((uint32_t)((ks + 1) * 32 + a_col)) ^ a_xor));
                    #pragma unroll
                    for (int nt = 0; nt < 4; nt++)
                        ldsm_x4(bf[nxt][nt],
                                bT + (uint32_t)(nt * 16 * 128)
                                   + (((uint32_t)((ks + 1) * 32 + b_col)) ^ b_xor));
                }
                #pragma unroll
                for (int mt = 0; mt < 4; mt++)
                    #pragma unroll
                    for (int nt = 0; nt < 4; nt++) {
                        mma16816(acc[mt][2 * nt],     af[cur][mt], &bf[cur][nt][0]);
                        mma16816(acc[mt][2 * nt + 1], af[cur][mt], &bf[cur][nt][2]);
                    }
            }
        }
    }

    // Epilogue: direct fp32 stores with bias
    const int qr = lane >> 2, qc = lane & 3;
    float bv[8][2];
    #pragma unroll
    for (int n = 0; n < 8; n++) {
        const int col = n0 + wn * 64 + n * 8 + qc * 2;
        bv[n][0] = __ldg(bias + col);
        bv[n][1] = __ldg(bias + col + 1);
    }
    #pragma unroll
    for (int mt = 0; mt < 4; mt++) {
        #pragma unroll
        for (int h = 0; h < 2; h++) {
            const int row = m0 + wm * 64 + mt * 16 + qr + h * 8;
            float* orow = out + (size_t)row * OUTDIM + n0 + wn * 64;
            #pragma unroll
            for (int n = 0; n < 8; n++) {
                float2 v;
                v.x = acc[mt][n][2 * h]     + bv[n][0];
                v.y = acc[mt][n][2 * h + 1] + bv[n][1];
                *reinterpret_cast<float2*>(orow + n * 8 + qc * 2) = v;
            }
        }
    }
}

// ---------------------------------------------------------------------------
// Harness entry
// ---------------------------------------------------------------------------
extern "C" void kernel_launch(void* const* d_in, const int* in_sizes, int n_in,
                              void* d_out, int out_size) {
    const float* x      = (const float*)d_in[0];
    const int*   Qw     = (const int*)d_in[1];
    const float* scales = (const float*)d_in[2];
    const float* bias   = (const float*)d_in[3];
    float*       out    = (float*)d_out;

    prep_kernel<<<XBLK + WBLK, 256>>>(x, Qw, scales);

    cudaFuncSetAttribute(gemm_kernel,
                         cudaFuncAttributeMaxDynamicSharedMemorySize, SMEM_BYTES);
    gemm_kernel<<<dim3(OUTDIM / BN, TOKENS / BM), 256, SMEM_BYTES>>>(out, bias);
}

// round 10
// speedup vs baseline: 1.0813x; 1.0813x over previous
#include <cuda_runtime.h>
#include <cuda_fp16.h>
#include <cstdint>
#include <cstddef>

// Problem sizes (fixed by the dataset)
static constexpr int TOKENS = 8192;
static constexpr int INDIM  = 4096;
static constexpr int OUTDIM = 4096;
static constexpr int GROUPS = 32;      // INDIM / 128

// fp16 staging buffers (static device allocs are allowed; cudaMalloc is not)
__device__ __half g_Xh[(size_t)TOKENS * INDIM];   // 64 MB
__device__ __half g_Wh[(size_t)OUTDIM * INDIM];   // 32 MB

// ---------------------------------------------------------------------------
// Fused prologue: blocks [0, XBLK) convert x -> fp16; the rest dequantize W.
// ---------------------------------------------------------------------------
static constexpr int XBLK = (TOKENS * (INDIM / 4)) / 256;    // 32768
static constexpr int WBLK = (OUTDIM * (INDIM / 4)) / 256;    // 16384

__global__ void __launch_bounds__(256)
prep_kernel(const float* __restrict__ x, const int* __restrict__ Q,
            const float* __restrict__ scales) {
    if (blockIdx.x < XBLK) {
        size_t i = (size_t)blockIdx.x * 256 + threadIdx.x;     // float4 index
        float4 v = reinterpret_cast<const float4*>(x)[i];
        __half2 h0 = __floats2half2_rn(v.x, v.y);
        __half2 h1 = __floats2half2_rn(v.z, v.w);
        uint2 u;
        u.x = *reinterpret_cast<uint32_t*>(&h0);
        u.y = *reinterpret_cast<uint32_t*>(&h1);
        reinterpret_cast<uint2*>(g_Xh)[i] = u;
    } else {
        size_t i = (size_t)(blockIdx.x - XBLK) * 256 + threadIdx.x;  // int4 idx
        int4 q = reinterpret_cast<const int4*>(Q)[i];
        size_t lin = i * 4;
        int o = (int)(lin >> 12);            // / 4096
        int k = (int)(lin & 4095);
        float s = __ldg(scales + o * GROUPS + (k >> 7));
        __half2 h0 = __floats2half2_rn((float)q.x * s, (float)q.y * s);
        __half2 h1 = __floats2half2_rn((float)q.z * s, (float)q.w * s);
        uint2 u;
        u.x = *reinterpret_cast<uint32_t*>(&h0);
        u.y = *reinterpret_cast<uint32_t*>(&h1);
        reinterpret_cast<uint2*>(g_Wh)[i] = u;
    }
}

// ---------------------------------------------------------------------------
// Helpers
// ---------------------------------------------------------------------------
__device__ __forceinline__ uint32_t smem_u32(const void* p) {
    uint32_t a;
    asm("{ .reg .u64 t; cvta.to.shared.u64 t, %1; cvt.u32.u64 %0, t; }"
        : "=r"(a) : "l"(p));
    return a;
}

__device__ __forceinline__ uint32_t sw128(uint32_t o) {
    return o ^ ((o >> 3) & 0x70);
}

__device__ __forceinline__ void ldsm_x4(uint32_t* r, uint32_t addr) {
    asm volatile("ldmatrix.sync.aligned.m8n8.x4.shared.b16 {%0,%1,%2,%3}, [%4];"
                 : "=r"(r[0]), "=r"(r[1]), "=r"(r[2]), "=r"(r[3])
                 : "r"(addr));
}

__device__ __forceinline__ void mma16816(float* c, const uint32_t* a,
                                         const uint32_t* b) {
    asm volatile(
        "mma.sync.aligned.m16n8k16.row.col.f32.f16.f16.f32 "
        "{%0,%1,%2,%3}, {%4,%5,%6,%7}, {%8,%9}, {%0,%1,%2,%3};"
        : "+f"(c[0]), "+f"(c[1]), "+f"(c[2]), "+f"(c[3])
        : "r"(a[0]), "r"(a[1]), "r"(a[2]), "r"(a[3]), "r"(b[0]), "r"(b[1]));
}

// ---------------------------------------------------------------------------
// GEMM: C[8192,4096] = Xh @ Wh^T + bias
// BM=128, BN=128, BK=64, 3 stages, 256 threads (8 warps, 2x4), warp tile
// 64x32, 2 CTAs/SM (16 warps/SM = 4 per SMSP for tensor-pipe latency hiding).
// ---------------------------------------------------------------------------
static constexpr int BM = 128;
static constexpr int BN = 128;
static constexpr int BK = 64;                 // halves; 128 bytes per row
static constexpr int STAGES = 3;
static constexpr int KITERS = INDIM / BK;     // 64
static constexpr int A_BYTES = BM * 128;      // 16384
static constexpr int STAGE_BYTES = A_BYTES + BN * 128;  // 32768
static constexpr int SMEM_BYTES = STAGES * STAGE_BYTES + 1024;  // 99328

__global__ void __launch_bounds__(256, 2)
gemm_kernel(float* __restrict__ out, const float* __restrict__ bias) {
    extern __shared__ char smem[];
    const uint32_t sb = (smem_u32(smem) + 1023u) & ~1023u;
    const int tid  = threadIdx.x;
    const int lane = tid & 31;
    const int wid  = tid >> 5;
    const int wm   = wid >> 2;    // 0..1 (64 rows each)
    const int wn   = wid & 3;     // 0..3 (32 cols each)
    const int n0   = blockIdx.x * BN;
    const int m0   = blockIdx.y * BM;

    // Stage loader: A 1024 + B 1024 16B-chunks over 256 threads (8 each)
    auto load_stage = [&](int s, int kiter) {
        const int k0 = kiter * BK;
        const uint32_t st = sb + s * STAGE_BYTES;
        #pragma unroll
        for (int c = tid; c < 2048; c += 256) {
            const int ch = c & 7;                 // 16B chunk within 128B row
            const __half* g;
            uint32_t soff;
            if (c < 1024) {                       // A rows m0..m0+127
                const int r = c >> 3;
                g = g_Xh + (size_t)(m0 + r) * INDIM + k0 + ch * 8;
                soff = st + sw128((uint32_t)(r * 128 + ch * 16));
            } else {                              // B rows n0..n0+127
                const int r = (c - 1024) >> 3;
                g = g_Wh + (size_t)(n0 + r) * INDIM + k0 + ch * 8;
                soff = st + A_BYTES + sw128((uint32_t)(r * 128 + ch * 16));
            }
            asm volatile("cp.async.cg.shared.global [%0], [%1], 16;"
                         :: "r"(soff), "l"(g) : "memory");
        }
        asm volatile("cp.async.commit_group;" ::: "memory");
    };

    // Per-thread ldmatrix address components
    const int a_row = lane & 15;                       // 0..15
    const int a_col = (lane >> 4) << 4;                // 0 or 16 bytes
    const uint32_t a_xor = (uint32_t)((a_row & 7) << 4);
    const int b_row = ((lane >> 4) << 3) | (lane & 7); // 0..15
    const int b_col = ((lane >> 3) & 1) << 4;          // 0 or 16 bytes
    const uint32_t b_xor = (uint32_t)((b_row & 7) << 4);

    float acc[4][4][4];   // [m16 tile][n8 tile][frag]
    #pragma unroll
    for (int mt = 0; mt < 4; mt++)
        #pragma unroll
        for (int n = 0; n < 4; n++)
            #pragma unroll
            for (int j = 0; j < 4; j++) acc[mt][n][j] = 0.0f;

    // Prologue: 2 stages in flight
    load_stage(0, 0);
    load_stage(1, 1);

    int s = 0;
    for (int i = 0; i < KITERS; i++) {
        asm volatile("cp.async.wait_group 1;" ::: "memory");
        __syncthreads();

        // Prefetch stage i+2 (buffer freed by the barrier above)
        if (i + 2 < KITERS) {
            load_stage(s == 0 ? 2 : s - 1, i + 2);   // (i+2)%3
        } else {
            asm volatile("cp.async.commit_group;" ::: "memory");
        }

        // Compute on stage s
        const uint32_t stg = sb + s * STAGE_BYTES;
        const uint32_t aT = stg + (uint32_t)((wm * 64 + a_row) * 128);
        const uint32_t bT = stg + A_BYTES + (uint32_t)((wn * 32 + b_row) * 128);

        #pragma unroll
        for (int ks = 0; ks < 4; ks++) {
            uint32_t af[4][4], bf[2][4];
            #pragma unroll
            for (int mt = 0; mt < 4; mt++)
                ldsm_x4(af[mt], aT + (uint32_t)(mt * 16 * 128)
                                   + (((uint32_t)(ks * 32 + a_col)) ^ a_xor));
            #pragma unroll
            for (int nt = 0; nt < 2; nt++)
                ldsm_x4(bf[nt], bT + (uint32_t)(nt * 16 * 128)
                                   + (((uint32_t)(ks * 32 + b_col)) ^ b_xor));
            #pragma unroll
            for (int mt = 0; mt < 4; mt++)
                #pragma unroll
                for (int nt = 0; nt < 2; nt++) {
                    mma16816(acc[mt][2 * nt],     af[mt], &bf[nt][0]);
                    mma16816(acc[mt][2 * nt + 1], af[mt], &bf[nt][2]);
                }
        }
        s = (s == STAGES - 1) ? 0 : s + 1;
    }

    // Epilogue: direct fp32 stores with bias
    const int qr = lane >> 2, qc = lane & 3;
    float bv[4][2];
    #pragma unroll
    for (int n = 0; n < 4; n++) {
        const int col = n0 + wn * 32 + n * 8 + qc * 2;
        bv[n][0] = __ldg(bias + col);
        bv[n][1] = __ldg(bias + col + 1);
    }
    #pragma unroll
    for (int mt = 0; mt < 4; mt++) {
        #pragma unroll
        for (int h = 0; h < 2; h++) {
            const int row = m0 + wm * 64 + mt * 16 + qr + h * 8;
            float* orow = out + (size_t)row * OUTDIM + n0 + wn * 32;
            #pragma unroll
            for (int n = 0; n < 4; n++) {
                float2 v;
                v.x = acc[mt][n][2 * h]     + bv[n][0];
                v.y = acc[mt][n][2 * h + 1] + bv[n][1];
                *reinterpret_cast<float2*>(orow + n * 8 + qc * 2) = v;
            }
        }
    }
}

// ---------------------------------------------------------------------------
// Harness entry
// ---------------------------------------------------------------------------
extern "C" void kernel_launch(void* const* d_in, const int* in_sizes, int n_in,
                              void* d_out, int out_size) {
    const float* x      = (const float*)d_in[0];
    const int*   Qw     = (const int*)d_in[1];
    const float* scales = (const float*)d_in[2];
    const float* bias   = (const float*)d_in[3];
    float*       out    = (float*)d_out;

    prep_kernel<<<XBLK + WBLK, 256>>>(x, Qw, scales);

    cudaFuncSetAttribute(gemm_kernel,
                         cudaFuncAttributeMaxDynamicSharedMemorySize, SMEM_BYTES);
    gemm_kernel<<<dim3(OUTDIM / BN, TOKENS / BM), 256, SMEM_BYTES>>>(out, bias);
}